// round 16
// baseline (speedup 1.0000x reference)
#include <cuda_runtime.h>
#include <cuda_bf16.h>
#include <cstdint>
#include <math.h>

#define SEQ 2048
#define DIM 3072
#define NH 24
#define HD 128
#define RANK 16
#define QKV_N (3 * DIM)
#define LORA_SCALE 1.0f
#define SEQW (SEQ / 2)

// ---------------- scratch (device globals; no allocations allowed) ----------
__device__ float g_qkv[(size_t)SEQ * QKV_N];
__device__ float g_o[(size_t)SEQ * DIM];

__device__ unsigned g_x2h[(size_t)SEQ * DIM / 2],   g_x2l[(size_t)SEQ * DIM / 2];
__device__ unsigned g_w1h[(size_t)QKV_N * DIM / 2], g_w1l[(size_t)QKV_N * DIM / 2];
__device__ unsigned g_w2h[(size_t)DIM * DIM / 2],   g_w2l[(size_t)DIM * DIM / 2];
__device__ unsigned g_o2h[(size_t)SEQ * DIM / 2],   g_o2l[(size_t)SEQ * DIM / 2];
__device__ unsigned g_u1h[QKV_N * RANK / 2],        g_u1l[QKV_N * RANK / 2];
__device__ unsigned g_u2h[DIM * RANK / 2],          g_u2l[DIM * RANK / 2];
__device__ unsigned g_xa2h[SEQ * RANK / 2],         g_xa2l[SEQ * RANK / 2];
__device__ unsigned g_ob2h[SEQ * RANK / 2],         g_ob2l[SEQ * RANK / 2];
__device__ unsigned g_q2h[(size_t)NH * SEQ * HD / 2], g_q2l[(size_t)NH * SEQ * HD / 2];
__device__ unsigned g_k2h[(size_t)NH * SEQ * HD / 2], g_k2l[(size_t)NH * SEQ * HD / 2];
__device__ unsigned g_v2h[(size_t)NH * HD * SEQW],    g_v2l[(size_t)NH * HD * SEQW];

// ---------------- helpers ----------------------------------------------------
__device__ __forceinline__ void mma_bf16(float* d, const unsigned* a, const unsigned* b)
{
    asm volatile(
        "mma.sync.aligned.m16n8k16.row.col.f32.bf16.bf16.f32 "
        "{%0,%1,%2,%3},{%4,%5,%6,%7},{%8,%9},{%0,%1,%2,%3};\n"
        : "+f"(d[0]), "+f"(d[1]), "+f"(d[2]), "+f"(d[3])
        : "r"(a[0]), "r"(a[1]), "r"(a[2]), "r"(a[3]), "r"(b[0]), "r"(b[1]));
}

__device__ __forceinline__ void ldsm4(unsigned* r, unsigned addr)
{
    asm volatile("ldmatrix.sync.aligned.m8n8.x4.shared.b16 {%0,%1,%2,%3}, [%4];"
                 : "=r"(r[0]), "=r"(r[1]), "=r"(r[2]), "=r"(r[3]) : "r"(addr));
}

__device__ __forceinline__ void cpa16(unsigned dst, const void* src)
{
    asm volatile("cp.async.cg.shared.global [%0], [%1], 16;" :: "r"(dst), "l"(src));
}
#define CP_COMMIT() asm volatile("cp.async.commit_group;")
#define CP_WAIT1()  asm volatile("cp.async.wait_group 1;")
#define CP_WAIT0()  asm volatile("cp.async.wait_group 0;")

__device__ __forceinline__ unsigned packbf(float v0, float v1)
{
    unsigned r;
    asm("cvt.rn.bf16x2.f32 %0, %1, %2;" : "=r"(r) : "f"(v1), "f"(v0));
    return r;
}
__device__ __forceinline__ float2 unpackbf(unsigned w)
{
    float2 f;
    f.x = __uint_as_float(w << 16);
    f.y = __uint_as_float(w & 0xffff0000u);
    return f;
}

__device__ __forceinline__ float exp2t(float x)
{
    x = fmaxf(x, -120.f);
    float r = rintf(x);
    float t = (x - r) * 0.6931471805599453f;
    float p = fmaf(t, 0.0083333333f, 0.041666666f);
    p = fmaf(t, p, 0.16666667f);
    p = fmaf(t, p, 0.5f);
    p = fmaf(t, p, 1.0f);
    p = fmaf(t, p, 1.0f);
    return __int_as_float(__float_as_int(p) + (((int)r) << 23));
}

__device__ __forceinline__ void pack_pair(const float4 v, unsigned* hi, unsigned* lo,
                                          size_t i)
{
    unsigned h0 = packbf(v.x, v.y), h1 = packbf(v.z, v.w);
    float2 a = unpackbf(h0), b = unpackbf(h1);
    ((uint2*)hi)[i] = make_uint2(h0, h1);
    ((uint2*)lo)[i] = make_uint2(packbf(v.x - a.x, v.y - a.y),
                                 packbf(v.z - b.x, v.w - b.y));
}

// ---------------- fp32 -> (hi, lo) bf16-pair pack -----------------------------
__global__ void __launch_bounds__(256) convert_pack_k(
    const float4* __restrict__ in, unsigned* __restrict__ hi,
    unsigned* __restrict__ lo, int n4)
{
    int i = blockIdx.x * 256 + threadIdx.x;
    if (i >= n4) return;
    pack_pair(in[i], hi, lo, i);
}

__global__ void __launch_bounds__(256) convert_pack2_k(
    const float4* __restrict__ inA, unsigned* __restrict__ hiA,
    unsigned* __restrict__ loA, int n4A,
    const float4* __restrict__ inB, unsigned* __restrict__ hiB,
    unsigned* __restrict__ loB, int n4B)
{
    int i = blockIdx.x * 256 + threadIdx.x;
    if (i < n4A) {
        pack_pair(inA[i], hiA, loA, i);
    } else {
        int j = i - n4A;
        if (j < n4B) pack_pair(inB[j], hiB, loB, j);
    }
}

// ---------------- LoRA down-projection, fused bf16 hi/lo pack -----------------
#define LDCH 512
__global__ void __launch_bounds__(256) lora_down_pack_k(
    const float* __restrict__ A, const float* __restrict__ D,
    unsigned* __restrict__ outh, unsigned* __restrict__ outl)
{
    __shared__ float Ds[16][LDCH + 4];
    const int m = blockIdx.x * 16 + (threadIdx.x >> 4);
    const int r = threadIdx.x & 15;
    float a0 = 0.f, a1 = 0.f, a2 = 0.f, a3 = 0.f;
    for (int k0 = 0; k0 < DIM; k0 += LDCH) {
        for (int i = threadIdx.x; i < 16 * (LDCH / 4); i += 256) {
            int rr = i >> 7, kk = (i & 127) * 4;
            *(float4*)&Ds[rr][kk] = *(const float4*)&D[(size_t)rr * DIM + k0 + kk];
        }
        __syncthreads();
        const float4* a4 = (const float4*)(A + (size_t)m * DIM + k0);
        const float4* d4 = (const float4*)&Ds[r][0];
#pragma unroll 4
        for (int k = 0; k < LDCH / 4; k += 4) {
            float4 va0 = a4[k],     vd0 = d4[k];
            float4 va1 = a4[k + 1], vd1 = d4[k + 1];
            float4 va2 = a4[k + 2], vd2 = d4[k + 2];
            float4 va3 = a4[k + 3], vd3 = d4[k + 3];
            a0 = fmaf(va0.x, vd0.x, a0); a0 = fmaf(va0.y, vd0.y, a0);
            a0 = fmaf(va0.z, vd0.z, a0); a0 = fmaf(va0.w, vd0.w, a0);
            a1 = fmaf(va1.x, vd1.x, a1); a1 = fmaf(va1.y, vd1.y, a1);
            a1 = fmaf(va1.z, vd1.z, a1); a1 = fmaf(va1.w, vd1.w, a1);
            a2 = fmaf(va2.x, vd2.x, a2); a2 = fmaf(va2.y, vd2.y, a2);
            a2 = fmaf(va2.z, vd2.z, a2); a2 = fmaf(va2.w, vd2.w, a2);
            a3 = fmaf(va3.x, vd3.x, a3); a3 = fmaf(va3.y, vd3.y, a3);
            a3 = fmaf(va3.z, vd3.z, a3); a3 = fmaf(va3.w, vd3.w, a3);
        }
        __syncthreads();
    }
    float acc = ((a0 + a1) + (a2 + a3)) * LORA_SCALE;
    float accn = __shfl_down_sync(0xffffffffu, acc, 1);
    if ((r & 1) == 0) {
        unsigned hw = packbf(acc, accn);
        float2 u = unpackbf(hw);
        outh[m * 8 + (r >> 1)] = hw;
        outl[m * 8 + (r >> 1)] = packbf(acc - u.x, accn - u.y);
    }
}

// ---------------- split-bf16 GEMM 128x128, swizzled 3-stage pipeline ----------
#define SWOFF(r, u) (((r) << 4) + (((u) ^ (((r) >> 1) & 3)) << 2))
#define SAH 0
#define SAL 2048
#define SBH 4096
#define SBL 6144
#define SSTW 8192
#define NSTG 3
#define GEMM_SMEM (NSTG * SSTW * 4)

__global__ void __launch_bounds__(256, 2) gemm_bf16s_lora_k(
    const unsigned* __restrict__ Ahg, const unsigned* __restrict__ Alg,
    const unsigned* __restrict__ Whg, const unsigned* __restrict__ Wlg,
    const float* __restrict__ bias,
    const unsigned* __restrict__ LAh, const unsigned* __restrict__ LAl,
    const unsigned* __restrict__ LUh, const unsigned* __restrict__ LUl,
    float* __restrict__ C, int N, int K)
{
    extern __shared__ unsigned smg[];
    const unsigned sb = (unsigned)__cvta_generic_to_shared(smg);
    const int Kw = K / 2;

    const int tid = threadIdx.x;
    const int lane = tid & 31, wid = tid >> 5;
    const int wm = (wid & 1) * 64, wn = (wid >> 1) * 32;
    const int gr = lane >> 2, gc = lane & 3;
    const int bm = blockIdx.y * 128, bn = blockIdx.x * 128;

    const int aro = lane & 15, au = (lane >> 4);
    const int bro = ((lane >> 4) << 3) + (lane & 7);
    const int bu = ((lane >> 3) & 1);

    const int lrow = tid >> 2, lu = tid & 3;
    const unsigned wsw = SWOFF(lrow, lu);
    const int lwq = lu * 4;

    float acc[4][4][4];
#pragma unroll
    for (int i = 0; i < 4; i++)
#pragma unroll
        for (int j = 0; j < 4; j++)
#pragma unroll
            for (int q = 0; q < 4; q++) acc[i][j][q] = 0.f;

#define G_ISSUE(K0, ST) do {                                               \
        unsigned base_ = sb + (ST) * (SSTW * 4);                           \
        _Pragma("unroll")                                                  \
        for (int i_ = 0; i_ < 2; i_++) {                                   \
            int r_ = lrow + i_ * 64;                                       \
            unsigned w_ = wsw + i_ * 1024;                                 \
            size_t ai_ = (size_t)(bm + r_) * Kw + (K0) + lwq;              \
            size_t bi_ = (size_t)(bn + r_) * Kw + (K0) + lwq;              \
            cpa16(base_ + (SAH + w_) * 4, Ahg + ai_);                      \
            cpa16(base_ + (SAL + w_) * 4, Alg + ai_);                      \
            cpa16(base_ + (SBH + w_) * 4, Whg + bi_);                      \
            cpa16(base_ + (SBL + w_) * 4, Wlg + bi_);                      \
        }                                                                  \
    } while (0)

#define G_STEP(BASE, KK) do {                                              \
        unsigned ah[4][4], al[4][4], bh[2][4], bl[2][4];                   \
        _Pragma("unroll")                                                  \
        for (int nj = 0; nj < 2; nj++) {                                   \
            int rr = wn + nj * 16 + bro;                                   \
            unsigned ba = (BASE) + (SBH + SWOFF(rr, (KK) * 2 + bu)) * 4;   \
            ldsm4(bh[nj], ba);                                             \
            ldsm4(bl[nj], ba + (SBL - SBH) * 4);                           \
        }                                                                  \
        _Pragma("unroll")                                                  \
        for (int mi = 0; mi < 4; mi++) {                                   \
            int rr = wm + mi * 16 + aro;                                   \
            unsigned aa = (BASE) + (SAH + SWOFF(rr, (KK) * 2 + au)) * 4;   \
            ldsm4(ah[mi], aa);                                             \
            ldsm4(al[mi], aa + (SAL - SAH) * 4);                           \
        }                                                                  \
        _Pragma("unroll")                                                  \
        for (int mi = 0; mi < 4; mi++)                                     \
            _Pragma("unroll")                                              \
            for (int ni = 0; ni < 4; ni++)                                 \
                mma_bf16(acc[mi][ni], ah[mi], &bh[ni >> 1][(ni & 1) * 2]); \
        _Pragma("unroll")                                                  \
        for (int mi = 0; mi < 4; mi++)                                     \
            _Pragma("unroll")                                              \
            for (int ni = 0; ni < 4; ni++)                                 \
                mma_bf16(acc[mi][ni], ah[mi], &bl[ni >> 1][(ni & 1) * 2]); \
        _Pragma("unroll")                                                  \
        for (int mi = 0; mi < 4; mi++)                                     \
            _Pragma("unroll")                                              \
            for (int ni = 0; ni < 4; ni++)                                 \
                mma_bf16(acc[mi][ni], al[mi], &bh[ni >> 1][(ni & 1) * 2]); \
    } while (0)

    const int nk = Kw / 16;
    G_ISSUE(0, 0);
    CP_COMMIT();
    G_ISSUE(16, 1);
    CP_COMMIT();

    int ist = 2;
    int cst = 0;
    for (int it = 0; it < nk; it++) {
        if (it < nk - 1) CP_WAIT1(); else CP_WAIT0();
        __syncthreads();
        unsigned cbase = sb + cst * (SSTW * 4);
        G_STEP(cbase, 0);
        if (it + 2 < nk) {
            G_ISSUE((it + 2) * 16, ist);
            CP_COMMIT();
        } else if (it + 2 == nk) {
            int r = tid >> 1, u = tid & 1;
            unsigned w0 = SWOFF(r, u);
            *(uint4*)(smg + ist * SSTW + SAH + w0) = *(const uint4*)&LAh[(size_t)(bm + r) * 8 + u * 4];
            *(uint4*)(smg + ist * SSTW + SAL + w0) = *(const uint4*)&LAl[(size_t)(bm + r) * 8 + u * 4];
            *(uint4*)(smg + ist * SSTW + SBH + w0) = *(const uint4*)&LUh[(size_t)(bn + r) * 8 + u * 4];
            *(uint4*)(smg + ist * SSTW + SBL + w0) = *(const uint4*)&LUl[(size_t)(bn + r) * 8 + u * 4];
        }
        G_STEP(cbase, 1);
        ist = (ist == 2) ? 0 : ist + 1;
        cst = (cst == 2) ? 0 : cst + 1;
    }

    __syncthreads();
    {
        unsigned cbase = sb + cst * (SSTW * 4);
        G_STEP(cbase, 0);
    }

#pragma unroll
    for (int mi = 0; mi < 4; mi++) {
        int row = bm + wm + mi * 16 + gr;
#pragma unroll
        for (int ni = 0; ni < 4; ni++) {
            int col = bn + wn + ni * 8 + gc * 2;
            float b0 = __ldg(&bias[col]), b1 = __ldg(&bias[col + 1]);
            float2 v0 = {acc[mi][ni][0] + b0, acc[mi][ni][1] + b1};
            float2 v1 = {acc[mi][ni][2] + b0, acc[mi][ni][3] + b1};
            *(float2*)&C[(size_t)row * N + col] = v0;
            *(float2*)&C[(size_t)(row + 8) * N + col] = v1;
        }
    }
}

// ---------------- split-bf16 GEMM 128x96 (proj: better wave fill) -------------
#define T96AH 0
#define T96AL 2048
#define T96BH 4096
#define T96BL 5632
#define T96STW 7168
#define GEMM96_SMEM (NSTG * T96STW * 4)

__global__ void __launch_bounds__(256, 2) gemm96_bf16s_lora_k(
    const unsigned* __restrict__ Ahg, const unsigned* __restrict__ Alg,
    const unsigned* __restrict__ Whg, const unsigned* __restrict__ Wlg,
    const float* __restrict__ bias,
    const unsigned* __restrict__ LAh, const unsigned* __restrict__ LAl,
    const unsigned* __restrict__ LUh, const unsigned* __restrict__ LUl,
    float* __restrict__ C, int N, int K)
{
    extern __shared__ unsigned smg[];
    const unsigned sb = (unsigned)__cvta_generic_to_shared(smg);
    const int Kw = K / 2;

    const int tid = threadIdx.x;
    const int lane = tid & 31, wid = tid >> 5;
    const int wm = (wid & 3) * 32, wn = (wid >> 2) * 48;
    const int gr = lane >> 2, gc = lane & 3;
    const int bm = blockIdx.y * 128, bn = blockIdx.x * 96;

    const int aro = lane & 15, au = (lane >> 4);
    const int bro = ((lane >> 4) << 3) + (lane & 7);
    const int bu = ((lane >> 3) & 1);

    const int lrow = tid >> 2, lu = tid & 3;
    const unsigned wsw = SWOFF(lrow, lu);
    const int lwq = lu * 4;

    float acc[2][6][4];
#pragma unroll
    for (int i = 0; i < 2; i++)
#pragma unroll
        for (int j = 0; j < 6; j++)
#pragma unroll
            for (int q = 0; q < 4; q++) acc[i][j][q] = 0.f;

#define G96_ISSUE(K0, ST) do {                                             \
        unsigned base_ = sb + (ST) * (T96STW * 4);                         \
        _Pragma("unroll")                                                  \
        for (int i_ = 0; i_ < 2; i_++) {                                   \
            int r_ = lrow + i_ * 64;                                       \
            unsigned w_ = wsw + i_ * 1024;                                 \
            size_t ai_ = (size_t)(bm + r_) * Kw + (K0) + lwq;              \
            cpa16(base_ + (T96AH + w_) * 4, Ahg + ai_);                    \
            cpa16(base_ + (T96AL + w_) * 4, Alg + ai_);                    \
        }                                                                  \
        for (int j_ = tid; j_ < 384; j_ += 256) {                          \
            int r_ = j_ >> 2, u_ = j_ & 3;                                 \
            size_t bi_ = (size_t)(bn + r_) * Kw + (K0) + u_ * 4;           \
            unsigned w_ = SWOFF(r_, u_);                                   \
            cpa16(base_ + (T96BH + w_) * 4, Whg + bi_);                    \
            cpa16(base_ + (T96BL + w_) * 4, Wlg + bi_);                    \
        }                                                                  \
    } while (0)

#define G96_STEP(BASE, KK) do {                                            \
        unsigned ah[2][4], al[2][4], bh[3][4], bl[3][4];                   \
        _Pragma("unroll")                                                  \
        for (int nj = 0; nj < 3; nj++) {                                   \
            int rr = wn + nj * 16 + bro;                                   \
            unsigned ba = (BASE) + (T96BH + SWOFF(rr, (KK) * 2 + bu)) * 4; \
            ldsm4(bh[nj], ba);                                             \
            ldsm4(bl[nj], ba + (T96BL - T96BH) * 4);                       \
        }                                                                  \
        _Pragma("unroll")                                                  \
        for (int mi = 0; mi < 2; mi++) {                                   \
            int rr = wm + mi * 16 + aro;                                   \
            unsigned aa = (BASE) + (T96AH + SWOFF(rr, (KK) * 2 + au)) * 4; \
            ldsm4(ah[mi], aa);                                             \
            ldsm4(al[mi], aa + (T96AL - T96AH) * 4);                       \
        }                                                                  \
        _Pragma("unroll")                                                  \
        for (int mi = 0; mi < 2; mi++)                                     \
            _Pragma("unroll")                                              \
            for (int ni = 0; ni < 6; ni++)                                 \
                mma_bf16(acc[mi][ni], ah[mi], &bh[ni >> 1][(ni & 1) * 2]); \
        _Pragma("unroll")                                                  \
        for (int mi = 0; mi < 2; mi++)                                     \
            _Pragma("unroll")                                              \
            for (int ni = 0; ni < 6; ni++)                                 \
                mma_bf16(acc[mi][ni], ah[mi], &bl[ni >> 1][(ni & 1) * 2]); \
        _Pragma("unroll")                                                  \
        for (int mi = 0; mi < 2; mi++)                                     \
            _Pragma("unroll")                                              \
            for (int ni = 0; ni < 6; ni++)                                 \
                mma_bf16(acc[mi][ni], al[mi], &bh[ni >> 1][(ni & 1) * 2]); \
    } while (0)

    const int nk = Kw / 16;
    G96_ISSUE(0, 0);
    CP_COMMIT();
    G96_ISSUE(16, 1);
    CP_COMMIT();

    int ist = 2;
    int cst = 0;
    for (int it = 0; it < nk; it++) {
        if (it < nk - 1) CP_WAIT1(); else CP_WAIT0();
        __syncthreads();
        unsigned cbase = sb + cst * (T96STW * 4);
        G96_STEP(cbase, 0);
        if (it + 2 < nk) {
            G96_ISSUE((it + 2) * 16, ist);
            CP_COMMIT();
        } else if (it + 2 == nk) {
            {
                int r = tid >> 1, u = tid & 1;
                unsigned w0 = SWOFF(r, u);
                *(uint4*)(smg + ist * T96STW + T96AH + w0) = *(const uint4*)&LAh[(size_t)(bm + r) * 8 + u * 4];
                *(uint4*)(smg + ist * T96STW + T96AL + w0) = *(const uint4*)&LAl[(size_t)(bm + r) * 8 + u * 4];
            }
            if (tid < 192) {
                int r = tid >> 1, u = tid & 1;
                unsigned w0 = SWOFF(r, u);
                *(uint4*)(smg + ist * T96STW + T96BH + w0) = *(const uint4*)&LUh[(size_t)(bn + r) * 8 + u * 4];
                *(uint4*)(smg + ist * T96STW + T96BL + w0) = *(const uint4*)&LUl[(size_t)(bn + r) * 8 + u * 4];
            }
        }
        G96_STEP(cbase, 1);
        ist = (ist == 2) ? 0 : ist + 1;
        cst = (cst == 2) ? 0 : cst + 1;
    }

    __syncthreads();
    {
        unsigned cbase = sb + cst * (T96STW * 4);
        G96_STEP(cbase, 0);
    }

#pragma unroll
    for (int mi = 0; mi < 2; mi++) {
        int row = bm + wm + mi * 16 + gr;
#pragma unroll
        for (int ni = 0; ni < 6; ni++) {
            int col = bn + wn + ni * 8 + gc * 2;
            float b0 = __ldg(&bias[col]), b1 = __ldg(&bias[col + 1]);
            float2 v0 = {acc[mi][ni][0] + b0, acc[mi][ni][1] + b1};
            float2 v1 = {acc[mi][ni][2] + b0, acc[mi][ni][3] + b1};
            *(float2*)&C[(size_t)row * N + col] = v0;
            *(float2*)&C[(size_t)(row + 8) * N + col] = v1;
        }
    }
}

// ---------------- QK RMSNorm + RoPE + packed repack ---------------------------
__global__ void __launch_bounds__(256) norm_rope_k(
    const float* __restrict__ pe,
    const float* __restrict__ q_scale, const float* __restrict__ k_scale)
{
    const int half = threadIdx.x >> 7;
    const int t = threadIdx.x & 127;
    const int l = blockIdx.x * 2 + half;
    const int h = blockIdx.y;

    const float* row = g_qkv + (size_t)l * QKV_N + h * HD;
    float qv = row[t], kv = row[DIM + t], vv = row[2 * DIM + t];

    __shared__ float red[2][8];
    __shared__ float qr[2][HD], kr[2][HD], qo_[2][HD], ko_[2][HD], vr[2][HD];

    float s1 = qv * qv, s2 = kv * kv;
#pragma unroll
    for (int o = 16; o > 0; o >>= 1) {
        s1 += __shfl_xor_sync(0xffffffffu, s1, o);
        s2 += __shfl_xor_sync(0xffffffffu, s2, o);
    }
    int w = (t >> 5);
    if ((t & 31) == 0) { red[half][w] = s1; red[half][4 + w] = s2; }
    __syncthreads();
    float msq = (red[half][0] + red[half][1] + red[half][2] + red[half][3]) * (1.f / HD);
    float msk = (red[half][4] + red[half][5] + red[half][6] + red[half][7]) * (1.f / HD);
    qr[half][t] = qv * rsqrtf(msq + 1e-6f) * q_scale[t];
    kr[half][t] = kv * rsqrtf(msk + 1e-6f) * k_scale[t];
    vr[half][t] = vv;
    __syncthreads();

    int i = t >> 1;
    const float* p = pe + ((size_t)l * (HD / 2) + i) * 4;
    float c = p[0], s = p[2];
    float q0 = qr[half][2 * i], q1 = qr[half][2 * i + 1];
    float k0 = kr[half][2 * i], k1 = kr[half][2 * i + 1];
    qo_[half][t] = (t & 1) ? fmaf(s, q0, c * q1) : fmaf(c, q0, -s * q1);
    ko_[half][t] = (t & 1) ? fmaf(s, k0, c * k1) : fmaf(c, k0, -s * k1);
    __syncthreads();

    if (t < 64) {
        size_t base = ((size_t)h * SEQ + l) * (HD / 2) + t;
        float a0 = qo_[half][2 * t], a1 = qo_[half][2 * t + 1];
        unsigned hq = packbf(a0, a1);
        float2 u = unpackbf(hq);
        g_q2h[base] = hq;
        g_q2l[base] = packbf(a0 - u.x, a1 - u.y);
        float b0 = ko_[half][2 * t], b1 = ko_[half][2 * t + 1];
        unsigned hk = packbf(b0, b1);
        u = unpackbf(hk);
        g_k2h[base] = hk;
        g_k2l[base] = packbf(b0 - u.x, b1 - u.y);
    }
    if (half == 0) {
        float v0 = vr[0][t], v1 = vr[1][t];
        unsigned hv = packbf(v0, v1);
        float2 u = unpackbf(hv);
        size_t base = ((size_t)h * HD + t) * SEQW + blockIdx.x;
        g_v2h[base] = hv;
        g_v2l[base] = packbf(v0 - u.x, v1 - u.y);
    }
}

// ---------------- flash attention: reg-Q + 3-stage single-sync pipeline -------
#define FBM 128
#define FBN 64
#define QSW 68
#define VSW 36
#define FKH 0
#define FKL 4352
#define FVH 8704
#define FVL 13312
#define FSTW 17920
#define FNSTG 3
#define FA_SMEM (FNSTG * FSTW * 4)

__global__ void __launch_bounds__(256) flash_k()
{
    extern __shared__ unsigned smf[];
    const unsigned sb = (unsigned)__cvta_generic_to_shared(smf);

    const int h = blockIdx.y;
    const int q0 = blockIdx.x * FBM;
    const int tid = threadIdx.x;
    const int lane = tid & 31, wid = tid >> 5;
    const int gr = lane >> 2, gc = lane & 3;
    const int rb = wid * 16;

    const int aro = lane & 15, aco = (lane >> 4) << 2;
    const int bro = ((lane >> 4) << 3) + (lane & 7), bco = ((lane >> 3) & 1) << 2;

#pragma unroll
    for (int i = 0; i < 8; i++) {
        int idx = tid + i * 256;
        int r = idx >> 4, wq = (idx & 15) * 4;
        size_t src = ((size_t)h * SEQ + q0 + r) * 64 + wq;
        *(uint4*)&smf[r * QSW + wq] = *(const uint4*)&g_q2h[src];
        *(uint4*)&smf[8704 + r * QSW + wq] = *(const uint4*)&g_q2l[src];
    }
    __syncthreads();
    unsigned qfh[8][4], qfl[8][4];
#pragma unroll
    for (int kk = 0; kk < 8; kk++) {
        unsigned qa = sb + ((rb + aro) * QSW + kk * 8 + aco) * 4;
        ldsm4(qfh[kk], qa);
        ldsm4(qfl[kk], qa + 8704 * 4);
    }
    __syncthreads();

#define F_ISSUE(KT, ST) do {                                                \
        unsigned base_ = sb + (ST) * (FSTW * 4);                            \
        _Pragma("unroll")                                                   \
        for (int i_ = 0; i_ < 4; i_++) {                                    \
            int idx_ = tid + i_ * 256;                                      \
            int r_ = idx_ >> 4, wq_ = (idx_ & 15) * 4;                      \
            size_t ks_ = ((size_t)h * SEQ + (KT) + r_) * 64 + wq_;          \
            cpa16(base_ + (FKH + r_ * QSW + wq_) * 4, g_k2h + ks_);         \
            cpa16(base_ + (FKL + r_ * QSW + wq_) * 4, g_k2l + ks_);         \
            int rv_ = idx_ >> 3, wv_ = (idx_ & 7) * 4;                      \
            size_t vs_ = ((size_t)h * HD + rv_) * SEQW + (KT) / 2 + wv_;    \
            cpa16(base_ + (FVH + rv_ * VSW + wv_) * 4, g_v2h + vs_);        \
            cpa16(base_ + (FVL + rv_ * VSW + wv_) * 4, g_v2l + vs_);        \
        }                                                                   \
    } while (0)

    float o[16][4];
#pragma unroll
    for (int i = 0; i < 16; i++)
#pragma unroll
        for (int j = 0; j < 4; j++) o[i][j] = 0.f;
    float m_lo = -1e30f, m_hi = -1e30f, l_lo = 0.f, l_hi = 0.f;
    const float SC2 = 0.088388347648318447f * 1.4426950408889634f;

    F_ISSUE(0, 0);
    CP_COMMIT();
    F_ISSUE(FBN, 1);
    CP_COMMIT();

    const int nkt = SEQ / FBN;
    int ist = 2, cst = 0;
    for (int it = 0; it < nkt; it++) {
        if (it < nkt - 1) CP_WAIT1(); else CP_WAIT0();
        __syncthreads();
        unsigned kbase = sb + cst * (FSTW * 4);

        float s[8][4];
#pragma unroll
        for (int i = 0; i < 8; i++)
#pragma unroll
            for (int j = 0; j < 4; j++) s[i][j] = 0.f;
#pragma unroll
        for (int kk = 0; kk < 8; kk++) {
#pragma unroll
            for (int nj = 0; nj < 4; nj++) {
                unsigned ka = kbase + (FKH + (nj * 16 + bro) * QSW + kk * 8 + bco) * 4;
                unsigned kh[4], kl[4];
                ldsm4(kh, ka);
                ldsm4(kl, ka + (FKL - FKH) * 4);
                mma_bf16(s[2 * nj],     qfh[kk], kh);
                mma_bf16(s[2 * nj],     qfh[kk], kl);
                mma_bf16(s[2 * nj],     qfl[kk], kh);
                mma_bf16(s[2 * nj + 1], qfh[kk], kh + 2);
                mma_bf16(s[2 * nj + 1], qfh[kk], kl + 2);
                mma_bf16(s[2 * nj + 1], qfl[kk], kh + 2);
            }
        }

        if (it + 2 < nkt) {
            F_ISSUE((it + 2) * FBN, ist);
            CP_COMMIT();
        }

        float rl = -1e30f, rh = -1e30f;
#pragma unroll
        for (int ni = 0; ni < 8; ni++) {
            rl = fmaxf(rl, fmaxf(s[ni][0], s[ni][1]));
            rh = fmaxf(rh, fmaxf(s[ni][2], s[ni][3]));
        }
        rl *= SC2; rh *= SC2;
        rl = fmaxf(rl, __shfl_xor_sync(0xffffffffu, rl, 1));
        rl = fmaxf(rl, __shfl_xor_sync(0xffffffffu, rl, 2));
        rh = fmaxf(rh, __shfl_xor_sync(0xffffffffu, rh, 1));
        rh = fmaxf(rh, __shfl_xor_sync(0xffffffffu, rh, 2));
        float mlo = fmaxf(m_lo, rl), mhi = fmaxf(m_hi, rh);
        float clo = exp2t(m_lo - mlo), chi = exp2t(m_hi - mhi);

        float suml = 0.f, sumh = 0.f;
#pragma unroll
        for (int ni = 0; ni < 8; ni++) {
            s[ni][0] = exp2t(fmaf(s[ni][0], SC2, -mlo));
            s[ni][1] = exp2t(fmaf(s[ni][1], SC2, -mlo));
            s[ni][2] = exp2t(fmaf(s[ni][2], SC2, -mhi));
            s[ni][3] = exp2t(fmaf(s[ni][3], SC2, -mhi));
            suml += s[ni][0] + s[ni][1];
            sumh += s[ni][2] + s[ni][3];
        }
        suml += __shfl_xor_sync(0xffffffffu, suml, 1);
        suml += __shfl_xor_sync(0xffffffffu, suml, 2);
        sumh += __shfl_xor_sync(0xffffffffu, sumh, 1);
        sumh += __shfl_xor_sync(0xffffffffu, sumh, 2);
        l_lo = l_lo * clo + suml;
        l_hi = l_hi * chi + sumh;
        m_lo = mlo; m_hi = mhi;

#pragma unroll
        for (int ni = 0; ni < 16; ni++) {
            o[ni][0] *= clo; o[ni][1] *= clo;
            o[ni][2] *= chi; o[ni][3] *= chi;
        }

#pragma unroll
        for (int kk = 0; kk < 4; kk++) {
            unsigned ph[4], pl[4];
            ph[0] = packbf(s[2 * kk][0], s[2 * kk][1]);
            ph[1] = packbf(s[2 * kk][2], s[2 * kk][3]);
            ph[2] = packbf(s[2 * kk + 1][0], s[2 * kk + 1][1]);
            ph[3] = packbf(s[2 * kk + 1][2], s[2 * kk + 1][3]);
            float2 u;
            u = unpackbf(ph[0]); pl[0] = packbf(s[2 * kk][0] - u.x, s[2 * kk][1] - u.y);
            u = unpackbf(ph[1]); pl[1] = packbf(s[2 * kk][2] - u.x, s[2 * kk][3] - u.y);
            u = unpackbf(ph[2]); pl[2] = packbf(s[2 * kk + 1][0] - u.x, s[2 * kk + 1][1] - u.y);
            u = unpackbf(ph[3]); pl[3] = packbf(s[2 * kk + 1][2] - u.x, s[2 * kk + 1][3] - u.y);
#pragma unroll
            for (int nj = 0; nj < 8; nj++) {
                unsigned va = kbase + (FVH + (nj * 16 + bro) * VSW + kk * 8 + bco) * 4;
                unsigned vh[4], vl[4];
                ldsm4(vh, va);
                ldsm4(vl, va + (FVL - FVH) * 4);
                mma_bf16(o[2 * nj],     ph, vh);
                mma_bf16(o[2 * nj],     ph, vl);
                mma_bf16(o[2 * nj],     pl, vh);
                mma_bf16(o[2 * nj + 1], ph, vh + 2);
                mma_bf16(o[2 * nj + 1], ph, vl + 2);
                mma_bf16(o[2 * nj + 1], pl, vh + 2);
            }
        }
        ist = (ist == 2) ? 0 : ist + 1;
        cst = (cst == 2) ? 0 : cst + 1;
    }

    float il = 1.f / l_lo, ih = 1.f / l_hi;
#pragma unroll
    for (int ni = 0; ni < 16; ni++) {
        int row = q0 + rb + gr;
        int col = h * HD + ni * 8 + gc * 2;
        float2 v0 = {o[ni][0] * il, o[ni][1] * il};
        float2 v1 = {o[ni][2] * ih, o[ni][3] * ih};
        *(float2*)&g_o[(size_t)row * DIM + col] = v0;
        *(float2*)&g_o[(size_t)(row + 8) * DIM + col] = v1;

        size_t wi0 = (size_t)row * (DIM / 2) + (col >> 1);
        size_t wi1 = (size_t)(row + 8) * (DIM / 2) + (col >> 1);
        unsigned h0 = packbf(v0.x, v0.y);
        float2 u0 = unpackbf(h0);
        g_o2h[wi0] = h0;
        g_o2l[wi0] = packbf(v0.x - u0.x, v0.y - u0.y);
        unsigned h1 = packbf(v1.x, v1.y);
        float2 u1 = unpackbf(h1);
        g_o2h[wi1] = h1;
        g_o2l[wi1] = packbf(v1.x - u1.x, v1.y - u1.y);
    }
}

// ---------------- launch: fork-join multi-stream overlap ----------------------
extern "C" void kernel_launch(void* const* d_in, const int* in_sizes, int n_in,
                              void* d_out, int out_size)
{
    const float* x         = (const float*)d_in[0];
    const float* pe        = (const float*)d_in[1];
    const float* qkv_w     = (const float*)d_in[2];
    const float* qkv_b     = (const float*)d_in[3];
    const float* proj_w    = (const float*)d_in[4];
    const float* proj_b    = (const float*)d_in[5];
    const float* qkv_down  = (const float*)d_in[6];
    const float* qkv_up    = (const float*)d_in[7];
    const float* proj_down = (const float*)d_in[8];
    const float* proj_up   = (const float*)d_in[9];
    const float* q_scale   = (const float*)d_in[10];
    const float* k_scale   = (const float*)d_in[11];
    float* out = (float*)d_out;
    (void)in_sizes; (void)n_in; (void)out_size;

    float *gqkv, *go;
    cudaGetSymbolAddress((void**)&gqkv, g_qkv);
    cudaGetSymbolAddress((void**)&go,   g_o);
    unsigned *x2h, *x2l, *w1h, *w1l, *w2h, *w2l, *o2h, *o2l;
    unsigned *u1h, *u1l, *u2h, *u2l, *xa2h, *xa2l, *ob2h, *ob2l;
    cudaGetSymbolAddress((void**)&x2h, g_x2h);   cudaGetSymbolAddress((void**)&x2l, g_x2l);
    cudaGetSymbolAddress((void**)&w1h, g_w1h);   cudaGetSymbolAddress((void**)&w1l, g_w1l);
    cudaGetSymbolAddress((void**)&w2h, g_w2h);   cudaGetSymbolAddress((void**)&w2l, g_w2l);
    cudaGetSymbolAddress((void**)&o2h, g_o2h);   cudaGetSymbolAddress((void**)&o2l, g_o2l);
    cudaGetSymbolAddress((void**)&u1h, g_u1h);   cudaGetSymbolAddress((void**)&u1l, g_u1l);
    cudaGetSymbolAddress((void**)&u2h, g_u2h);   cudaGetSymbolAddress((void**)&u2l, g_u2l);
    cudaGetSymbolAddress((void**)&xa2h, g_xa2h); cudaGetSymbolAddress((void**)&xa2l, g_xa2l);
    cudaGetSymbolAddress((void**)&ob2h, g_ob2h); cudaGetSymbolAddress((void**)&ob2l, g_ob2l);

    cudaFuncSetAttribute(flash_k, cudaFuncAttributeMaxDynamicSharedMemorySize,
                         (int)FA_SMEM);
    cudaFuncSetAttribute(gemm_bf16s_lora_k, cudaFuncAttributeMaxDynamicSharedMemorySize,
                         (int)GEMM_SMEM);
    cudaFuncSetAttribute(gemm96_bf16s_lora_k, cudaFuncAttributeMaxDynamicSharedMemorySize,
                         (int)GEMM96_SMEM);

    const int n4x  = (int)((size_t)SEQ * DIM / 4);
    const int n4w1 = (int)((size_t)QKV_N * DIM / 4);
    const int n4u1 = QKV_N * RANK / 4;
    const int n4w2 = (int)((size_t)DIM * DIM / 4);
    const int n4u2 = DIM * RANK / 4;

    // streams/events created once, reused (no device memory involved)
    static cudaStream_t s1 = 0, s2 = 0;
    static cudaEvent_t eRoot = 0, eS1 = 0, eS2 = 0;
    if (s1 == 0) {
        cudaStreamCreateWithFlags(&s1, cudaStreamNonBlocking);
        cudaStreamCreateWithFlags(&s2, cudaStreamNonBlocking);
        cudaEventCreateWithFlags(&eRoot, cudaEventDisableTiming);
        cudaEventCreateWithFlags(&eS1, cudaEventDisableTiming);
        cudaEventCreateWithFlags(&eS2, cudaEventDisableTiming);
    }

    // fork
    cudaEventRecord(eRoot, 0);
    cudaStreamWaitEvent(s1, eRoot, 0);
    cudaStreamWaitEvent(s2, eRoot, 0);

    // s1: pack x, lora-down(x)+pack   (qkv GEMM A-side operands)
    convert_pack_k<<<(n4x + 255) / 256, 256, 0, s1>>>((const float4*)x, x2h, x2l, n4x);
    lora_down_pack_k<<<SEQ / 16, 256, 0, s1>>>(x, qkv_down, xa2h, xa2l);
    cudaEventRecord(eS1, s1);

    // s2: pack proj_w + proj_up       (needed only by the final proj GEMM)
    convert_pack2_k<<<(n4w2 + n4u2 + 255) / 256, 256, 0, s2>>>(
        (const float4*)proj_w, w2h, w2l, n4w2,
        (const float4*)proj_up, u2h, u2l, n4u2);
    cudaEventRecord(eS2, s2);

    // default: pack qkv_w + qkv_up (runs concurrently with s1/s2)
    convert_pack2_k<<<(n4w1 + n4u1 + 255) / 256, 256>>>(
        (const float4*)qkv_w, w1h, w1l, n4w1,
        (const float4*)qkv_up, u1h, u1l, n4u1);

    // join s1, then the main chain on the default stream
    cudaStreamWaitEvent(0, eS1, 0);
    gemm_bf16s_lora_k<<<dim3(QKV_N / 128, SEQ / 128), 256, GEMM_SMEM>>>(
        x2h, x2l, w1h, w1l, qkv_b, xa2h, xa2l, u1h, u1l, gqkv, QKV_N, DIM);
    norm_rope_k<<<dim3(SEQ / 2, NH), 256>>>(pe, q_scale, k_scale);
    flash_k<<<dim3(SEQ / FBM, NH), 256, FA_SMEM>>>();
    lora_down_pack_k<<<SEQ / 16, 256>>>(go, proj_down, ob2h, ob2l);

    // join s2, then proj GEMM
    cudaStreamWaitEvent(0, eS2, 0);
    gemm96_bf16s_lora_k<<<dim3(DIM / 96, SEQ / 128), 256, GEMM96_SMEM>>>(
        o2h, o2l, w2h, w2l, proj_b, ob2h, ob2l, u2h, u2l, out, DIM, DIM);
}

// round 17
// speedup vs baseline: 1.0512x; 1.0512x over previous
#include <cuda_runtime.h>
#include <cuda_bf16.h>
#include <cstdint>
#include <math.h>

#define SEQ 2048
#define DIM 3072
#define NH 24
#define HD 128
#define RANK 16
#define QKV_N (3 * DIM)
#define LORA_SCALE 1.0f
#define SEQW (SEQ / 2)

// ---------------- scratch (device globals; no allocations allowed) ----------
__device__ float g_qkv[(size_t)SEQ * QKV_N];
__device__ float g_o[(size_t)SEQ * DIM];

__device__ unsigned g_x2h[(size_t)SEQ * DIM / 2],   g_x2l[(size_t)SEQ * DIM / 2];
__device__ unsigned g_w1h[(size_t)QKV_N * DIM / 2], g_w1l[(size_t)QKV_N * DIM / 2];
__device__ unsigned g_w2h[(size_t)DIM * DIM / 2],   g_w2l[(size_t)DIM * DIM / 2];
__device__ unsigned g_o2h[(size_t)SEQ * DIM / 2],   g_o2l[(size_t)SEQ * DIM / 2];
__device__ unsigned g_u1h[QKV_N * RANK / 2],        g_u1l[QKV_N * RANK / 2];
__device__ unsigned g_u2h[DIM * RANK / 2],          g_u2l[DIM * RANK / 2];
__device__ unsigned g_xa2h[SEQ * RANK / 2],         g_xa2l[SEQ * RANK / 2];
__device__ unsigned g_ob2h[SEQ * RANK / 2],         g_ob2l[SEQ * RANK / 2];
__device__ unsigned g_q2h[(size_t)NH * SEQ * HD / 2], g_q2l[(size_t)NH * SEQ * HD / 2];
__device__ unsigned g_k2h[(size_t)NH * SEQ * HD / 2], g_k2l[(size_t)NH * SEQ * HD / 2];
__device__ unsigned g_v2h[(size_t)NH * HD * SEQW],    g_v2l[(size_t)NH * HD * SEQW];

// ---------------- helpers ----------------------------------------------------
__device__ __forceinline__ void mma_bf16(float* d, const unsigned* a, const unsigned* b)
{
    asm volatile(
        "mma.sync.aligned.m16n8k16.row.col.f32.bf16.bf16.f32 "
        "{%0,%1,%2,%3},{%4,%5,%6,%7},{%8,%9},{%0,%1,%2,%3};\n"
        : "+f"(d[0]), "+f"(d[1]), "+f"(d[2]), "+f"(d[3])
        : "r"(a[0]), "r"(a[1]), "r"(a[2]), "r"(a[3]), "r"(b[0]), "r"(b[1]));
}

__device__ __forceinline__ void ldsm4(unsigned* r, unsigned addr)
{
    asm volatile("ldmatrix.sync.aligned.m8n8.x4.shared.b16 {%0,%1,%2,%3}, [%4];"
                 : "=r"(r[0]), "=r"(r[1]), "=r"(r[2]), "=r"(r[3]) : "r"(addr));
}

__device__ __forceinline__ void cpa16(unsigned dst, const void* src)
{
    asm volatile("cp.async.cg.shared.global [%0], [%1], 16;" :: "r"(dst), "l"(src));
}
#define CP_COMMIT() asm volatile("cp.async.commit_group;")
#define CP_WAIT1()  asm volatile("cp.async.wait_group 1;")
#define CP_WAIT0()  asm volatile("cp.async.wait_group 0;")

__device__ __forceinline__ unsigned packbf(float v0, float v1)
{
    unsigned r;
    asm("cvt.rn.bf16x2.f32 %0, %1, %2;" : "=r"(r) : "f"(v1), "f"(v0));
    return r;
}
__device__ __forceinline__ float2 unpackbf(unsigned w)
{
    float2 f;
    f.x = __uint_as_float(w << 16);
    f.y = __uint_as_float(w & 0xffff0000u);
    return f;
}

__device__ __forceinline__ float exp2t(float x)
{
    x = fmaxf(x, -120.f);
    float r = rintf(x);
    float t = (x - r) * 0.6931471805599453f;
    float p = fmaf(t, 0.0083333333f, 0.041666666f);
    p = fmaf(t, p, 0.16666667f);
    p = fmaf(t, p, 0.5f);
    p = fmaf(t, p, 1.0f);
    p = fmaf(t, p, 1.0f);
    return __int_as_float(__float_as_int(p) + (((int)r) << 23));
}

__device__ __forceinline__ void pack_pair(const float4 v, unsigned* hi, unsigned* lo,
                                          size_t i)
{
    unsigned h0 = packbf(v.x, v.y), h1 = packbf(v.z, v.w);
    float2 a = unpackbf(h0), b = unpackbf(h1);
    ((uint2*)hi)[i] = make_uint2(h0, h1);
    ((uint2*)lo)[i] = make_uint2(packbf(v.x - a.x, v.y - a.y),
                                 packbf(v.z - b.x, v.w - b.y));
}

// ---------------- fp32 -> (hi, lo) bf16-pair pack -----------------------------
__global__ void __launch_bounds__(256) convert_pack_k(
    const float4* __restrict__ in, unsigned* __restrict__ hi,
    unsigned* __restrict__ lo, int n4)
{
    int i = blockIdx.x * 256 + threadIdx.x;
    if (i >= n4) return;
    pack_pair(in[i], hi, lo, i);
}

__global__ void __launch_bounds__(256) convert_pack2_k(
    const float4* __restrict__ inA, unsigned* __restrict__ hiA,
    unsigned* __restrict__ loA, int n4A,
    const float4* __restrict__ inB, unsigned* __restrict__ hiB,
    unsigned* __restrict__ loB, int n4B)
{
    int i = blockIdx.x * 256 + threadIdx.x;
    if (i < n4A) {
        pack_pair(inA[i], hiA, loA, i);
    } else {
        int j = i - n4A;
        if (j < n4B) pack_pair(inB[j], hiB, loB, j);
    }
}

// ---------------- LoRA down-projection, fused bf16 hi/lo pack -----------------
// 8 tokens/CTA x 128 threads, grid 256: fills all SMs (was 128 CTAs)
#define LDCH 512
__global__ void __launch_bounds__(128) lora_down_pack_k(
    const float* __restrict__ A, const float* __restrict__ D,
    unsigned* __restrict__ outh, unsigned* __restrict__ outl)
{
    __shared__ float Ds[16][LDCH + 4];
    const int m = blockIdx.x * 8 + (threadIdx.x >> 4);
    const int r = threadIdx.x & 15;
    float a0 = 0.f, a1 = 0.f, a2 = 0.f, a3 = 0.f;
    for (int k0 = 0; k0 < DIM; k0 += LDCH) {
        for (int i = threadIdx.x; i < 16 * (LDCH / 4); i += 128) {
            int rr = i >> 7, kk = (i & 127) * 4;
            *(float4*)&Ds[rr][kk] = *(const float4*)&D[(size_t)rr * DIM + k0 + kk];
        }
        __syncthreads();
        const float4* a4 = (const float4*)(A + (size_t)m * DIM + k0);
        const float4* d4 = (const float4*)&Ds[r][0];
#pragma unroll 4
        for (int k = 0; k < LDCH / 4; k += 4) {
            float4 va0 = a4[k],     vd0 = d4[k];
            float4 va1 = a4[k + 1], vd1 = d4[k + 1];
            float4 va2 = a4[k + 2], vd2 = d4[k + 2];
            float4 va3 = a4[k + 3], vd3 = d4[k + 3];
            a0 = fmaf(va0.x, vd0.x, a0); a0 = fmaf(va0.y, vd0.y, a0);
            a0 = fmaf(va0.z, vd0.z, a0); a0 = fmaf(va0.w, vd0.w, a0);
            a1 = fmaf(va1.x, vd1.x, a1); a1 = fmaf(va1.y, vd1.y, a1);
            a1 = fmaf(va1.z, vd1.z, a1); a1 = fmaf(va1.w, vd1.w, a1);
            a2 = fmaf(va2.x, vd2.x, a2); a2 = fmaf(va2.y, vd2.y, a2);
            a2 = fmaf(va2.z, vd2.z, a2); a2 = fmaf(va2.w, vd2.w, a2);
            a3 = fmaf(va3.x, vd3.x, a3); a3 = fmaf(va3.y, vd3.y, a3);
            a3 = fmaf(va3.z, vd3.z, a3); a3 = fmaf(va3.w, vd3.w, a3);
        }
        __syncthreads();
    }
    float acc = ((a0 + a1) + (a2 + a3)) * LORA_SCALE;
    float accn = __shfl_down_sync(0xffffffffu, acc, 1);
    if ((r & 1) == 0) {
        unsigned hw = packbf(acc, accn);
        float2 u = unpackbf(hw);
        outh[m * 8 + (r >> 1)] = hw;
        outl[m * 8 + (r >> 1)] = packbf(acc - u.x, accn - u.y);
    }
}

// ---------------- split-bf16 GEMM 128x128, swizzled 3-stage pipeline ----------
#define SWOFF(r, u) (((r) << 4) + (((u) ^ (((r) >> 1) & 3)) << 2))
#define SAH 0
#define SAL 2048
#define SBH 4096
#define SBL 6144
#define SSTW 8192
#define NSTG 3
#define GEMM_SMEM (NSTG * SSTW * 4)

__global__ void __launch_bounds__(256, 2) gemm_bf16s_lora_k(
    const unsigned* __restrict__ Ahg, const unsigned* __restrict__ Alg,
    const unsigned* __restrict__ Whg, const unsigned* __restrict__ Wlg,
    const float* __restrict__ bias,
    const unsigned* __restrict__ LAh, const unsigned* __restrict__ LAl,
    const unsigned* __restrict__ LUh, const unsigned* __restrict__ LUl,
    float* __restrict__ C, int N, int K)
{
    extern __shared__ unsigned smg[];
    const unsigned sb = (unsigned)__cvta_generic_to_shared(smg);
    const int Kw = K / 2;

    const int tid = threadIdx.x;
    const int lane = tid & 31, wid = tid >> 5;
    const int wm = (wid & 1) * 64, wn = (wid >> 1) * 32;
    const int gr = lane >> 2, gc = lane & 3;
    const int bm = blockIdx.y * 128, bn = blockIdx.x * 128;

    const int aro = lane & 15, au = (lane >> 4);
    const int bro = ((lane >> 4) << 3) + (lane & 7);
    const int bu = ((lane >> 3) & 1);

    const int lrow = tid >> 2, lu = tid & 3;
    const unsigned wsw = SWOFF(lrow, lu);
    const int lwq = lu * 4;

    float acc[4][4][4];
#pragma unroll
    for (int i = 0; i < 4; i++)
#pragma unroll
        for (int j = 0; j < 4; j++)
#pragma unroll
            for (int q = 0; q < 4; q++) acc[i][j][q] = 0.f;

#define G_ISSUE(K0, ST) do {                                               \
        unsigned base_ = sb + (ST) * (SSTW * 4);                           \
        _Pragma("unroll")                                                  \
        for (int i_ = 0; i_ < 2; i_++) {                                   \
            int r_ = lrow + i_ * 64;                                       \
            unsigned w_ = wsw + i_ * 1024;                                 \
            size_t ai_ = (size_t)(bm + r_) * Kw + (K0) + lwq;              \
            size_t bi_ = (size_t)(bn + r_) * Kw + (K0) + lwq;              \
            cpa16(base_ + (SAH + w_) * 4, Ahg + ai_);                      \
            cpa16(base_ + (SAL + w_) * 4, Alg + ai_);                      \
            cpa16(base_ + (SBH + w_) * 4, Whg + bi_);                      \
            cpa16(base_ + (SBL + w_) * 4, Wlg + bi_);                      \
        }                                                                  \
    } while (0)

#define G_STEP(BASE, KK) do {                                              \
        unsigned ah[4][4], al[4][4], bh[2][4], bl[2][4];                   \
        _Pragma("unroll")                                                  \
        for (int nj = 0; nj < 2; nj++) {                                   \
            int rr = wn + nj * 16 + bro;                                   \
            unsigned ba = (BASE) + (SBH + SWOFF(rr, (KK) * 2 + bu)) * 4;   \
            ldsm4(bh[nj], ba);                                             \
            ldsm4(bl[nj], ba + (SBL - SBH) * 4);                           \
        }                                                                  \
        _Pragma("unroll")                                                  \
        for (int mi = 0; mi < 4; mi++) {                                   \
            int rr = wm + mi * 16 + aro;                                   \
            unsigned aa = (BASE) + (SAH + SWOFF(rr, (KK) * 2 + au)) * 4;   \
            ldsm4(ah[mi], aa);                                             \
            ldsm4(al[mi], aa + (SAL - SAH) * 4);                           \
        }                                                                  \
        _Pragma("unroll")                                                  \
        for (int mi = 0; mi < 4; mi++)                                     \
            _Pragma("unroll")                                              \
            for (int ni = 0; ni < 4; ni++)                                 \
                mma_bf16(acc[mi][ni], ah[mi], &bh[ni >> 1][(ni & 1) * 2]); \
        _Pragma("unroll")                                                  \
        for (int mi = 0; mi < 4; mi++)                                     \
            _Pragma("unroll")                                              \
            for (int ni = 0; ni < 4; ni++)                                 \
                mma_bf16(acc[mi][ni], ah[mi], &bl[ni >> 1][(ni & 1) * 2]); \
        _Pragma("unroll")                                                  \
        for (int mi = 0; mi < 4; mi++)                                     \
            _Pragma("unroll")                                              \
            for (int ni = 0; ni < 4; ni++)                                 \
                mma_bf16(acc[mi][ni], al[mi], &bh[ni >> 1][(ni & 1) * 2]); \
    } while (0)

    const int nk = Kw / 16;
    G_ISSUE(0, 0);
    CP_COMMIT();
    G_ISSUE(16, 1);
    CP_COMMIT();

    int ist = 2;
    int cst = 0;
    for (int it = 0; it < nk; it++) {
        if (it < nk - 1) CP_WAIT1(); else CP_WAIT0();
        __syncthreads();
        unsigned cbase = sb + cst * (SSTW * 4);
        G_STEP(cbase, 0);
        if (it + 2 < nk) {
            G_ISSUE((it + 2) * 16, ist);
            CP_COMMIT();
        } else if (it + 2 == nk) {
            int r = tid >> 1, u = tid & 1;
            unsigned w0 = SWOFF(r, u);
            *(uint4*)(smg + ist * SSTW + SAH + w0) = *(const uint4*)&LAh[(size_t)(bm + r) * 8 + u * 4];
            *(uint4*)(smg + ist * SSTW + SAL + w0) = *(const uint4*)&LAl[(size_t)(bm + r) * 8 + u * 4];
            *(uint4*)(smg + ist * SSTW + SBH + w0) = *(const uint4*)&LUh[(size_t)(bn + r) * 8 + u * 4];
            *(uint4*)(smg + ist * SSTW + SBL + w0) = *(const uint4*)&LUl[(size_t)(bn + r) * 8 + u * 4];
        }
        G_STEP(cbase, 1);
        ist = (ist == 2) ? 0 : ist + 1;
        cst = (cst == 2) ? 0 : cst + 1;
    }

    __syncthreads();
    {
        unsigned cbase = sb + cst * (SSTW * 4);
        G_STEP(cbase, 0);
    }

#pragma unroll
    for (int mi = 0; mi < 4; mi++) {
        int row = bm + wm + mi * 16 + gr;
#pragma unroll
        for (int ni = 0; ni < 4; ni++) {
            int col = bn + wn + ni * 8 + gc * 2;
            float b0 = __ldg(&bias[col]), b1 = __ldg(&bias[col + 1]);
            float2 v0 = {acc[mi][ni][0] + b0, acc[mi][ni][1] + b1};
            float2 v1 = {acc[mi][ni][2] + b0, acc[mi][ni][3] + b1};
            *(float2*)&C[(size_t)row * N + col] = v0;
            *(float2*)&C[(size_t)(row + 8) * N + col] = v1;
        }
    }
}

// ---------------- split-bf16 GEMM 128x96 (proj: better wave fill) -------------
#define T96AH 0
#define T96AL 2048
#define T96BH 4096
#define T96BL 5632
#define T96STW 7168
#define GEMM96_SMEM (NSTG * T96STW * 4)

__global__ void __launch_bounds__(256, 2) gemm96_bf16s_lora_k(
    const unsigned* __restrict__ Ahg, const unsigned* __restrict__ Alg,
    const unsigned* __restrict__ Whg, const unsigned* __restrict__ Wlg,
    const float* __restrict__ bias,
    const unsigned* __restrict__ LAh, const unsigned* __restrict__ LAl,
    const unsigned* __restrict__ LUh, const unsigned* __restrict__ LUl,
    float* __restrict__ C, int N, int K)
{
    extern __shared__ unsigned smg[];
    const unsigned sb = (unsigned)__cvta_generic_to_shared(smg);
    const int Kw = K / 2;

    const int tid = threadIdx.x;
    const int lane = tid & 31, wid = tid >> 5;
    const int wm = (wid & 3) * 32, wn = (wid >> 2) * 48;
    const int gr = lane >> 2, gc = lane & 3;
    const int bm = blockIdx.y * 128, bn = blockIdx.x * 96;

    const int aro = lane & 15, au = (lane >> 4);
    const int bro = ((lane >> 4) << 3) + (lane & 7);
    const int bu = ((lane >> 3) & 1);

    const int lrow = tid >> 2, lu = tid & 3;
    const unsigned wsw = SWOFF(lrow, lu);
    const int lwq = lu * 4;

    float acc[2][6][4];
#pragma unroll
    for (int i = 0; i < 2; i++)
#pragma unroll
        for (int j = 0; j < 6; j++)
#pragma unroll
            for (int q = 0; q < 4; q++) acc[i][j][q] = 0.f;

#define G96_ISSUE(K0, ST) do {                                             \
        unsigned base_ = sb + (ST) * (T96STW * 4);                         \
        _Pragma("unroll")                                                  \
        for (int i_ = 0; i_ < 2; i_++) {                                   \
            int r_ = lrow + i_ * 64;                                       \
            unsigned w_ = wsw + i_ * 1024;                                 \
            size_t ai_ = (size_t)(bm + r_) * Kw + (K0) + lwq;              \
            cpa16(base_ + (T96AH + w_) * 4, Ahg + ai_);                    \
            cpa16(base_ + (T96AL + w_) * 4, Alg + ai_);                    \
        }                                                                  \
        for (int j_ = tid; j_ < 384; j_ += 256) {                          \
            int r_ = j_ >> 2, u_ = j_ & 3;                                 \
            size_t bi_ = (size_t)(bn + r_) * Kw + (K0) + u_ * 4;           \
            unsigned w_ = SWOFF(r_, u_);                                   \
            cpa16(base_ + (T96BH + w_) * 4, Whg + bi_);                    \
            cpa16(base_ + (T96BL + w_) * 4, Wlg + bi_);                    \
        }                                                                  \
    } while (0)

#define G96_STEP(BASE, KK) do {                                            \
        unsigned ah[2][4], al[2][4], bh[3][4], bl[3][4];                   \
        _Pragma("unroll")                                                  \
        for (int nj = 0; nj < 3; nj++) {                                   \
            int rr = wn + nj * 16 + bro;                                   \
            unsigned ba = (BASE) + (T96BH + SWOFF(rr, (KK) * 2 + bu)) * 4; \
            ldsm4(bh[nj], ba);                                             \
            ldsm4(bl[nj], ba + (T96BL - T96BH) * 4);                       \
        }                                                                  \
        _Pragma("unroll")                                                  \
        for (int mi = 0; mi < 2; mi++) {                                   \
            int rr = wm + mi * 16 + aro;                                   \
            unsigned aa = (BASE) + (T96AH + SWOFF(rr, (KK) * 2 + au)) * 4; \
            ldsm4(ah[mi], aa);                                             \
            ldsm4(al[mi], aa + (T96AL - T96AH) * 4);                       \
        }                                                                  \
        _Pragma("unroll")                                                  \
        for (int mi = 0; mi < 2; mi++)                                     \
            _Pragma("unroll")                                              \
            for (int ni = 0; ni < 6; ni++)                                 \
                mma_bf16(acc[mi][ni], ah[mi], &bh[ni >> 1][(ni & 1) * 2]); \
        _Pragma("unroll")                                                  \
        for (int mi = 0; mi < 2; mi++)                                     \
            _Pragma("unroll")                                              \
            for (int ni = 0; ni < 6; ni++)                                 \
                mma_bf16(acc[mi][ni], ah[mi], &bl[ni >> 1][(ni & 1) * 2]); \
        _Pragma("unroll")                                                  \
        for (int mi = 0; mi < 2; mi++)                                     \
            _Pragma("unroll")                                              \
            for (int ni = 0; ni < 6; ni++)                                 \
                mma_bf16(acc[mi][ni], al[mi], &bh[ni >> 1][(ni & 1) * 2]); \
    } while (0)

    const int nk = Kw / 16;
    G96_ISSUE(0, 0);
    CP_COMMIT();
    G96_ISSUE(16, 1);
    CP_COMMIT();

    int ist = 2;
    int cst = 0;
    for (int it = 0; it < nk; it++) {
        if (it < nk - 1) CP_WAIT1(); else CP_WAIT0();
        __syncthreads();
        unsigned cbase = sb + cst * (T96STW * 4);
        G96_STEP(cbase, 0);
        if (it + 2 < nk) {
            G96_ISSUE((it + 2) * 16, ist);
            CP_COMMIT();
        } else if (it + 2 == nk) {
            {
                int r = tid >> 1, u = tid & 1;
                unsigned w0 = SWOFF(r, u);
                *(uint4*)(smg + ist * T96STW + T96AH + w0) = *(const uint4*)&LAh[(size_t)(bm + r) * 8 + u * 4];
                *(uint4*)(smg + ist * T96STW + T96AL + w0) = *(const uint4*)&LAl[(size_t)(bm + r) * 8 + u * 4];
            }
            if (tid < 192) {
                int r = tid >> 1, u = tid & 1;
                unsigned w0 = SWOFF(r, u);
                *(uint4*)(smg + ist * T96STW + T96BH + w0) = *(const uint4*)&LUh[(size_t)(bn + r) * 8 + u * 4];
                *(uint4*)(smg + ist * T96STW + T96BL + w0) = *(const uint4*)&LUl[(size_t)(bn + r) * 8 + u * 4];
            }
        }
        G96_STEP(cbase, 1);
        ist = (ist == 2) ? 0 : ist + 1;
        cst = (cst == 2) ? 0 : cst + 1;
    }

    __syncthreads();
    {
        unsigned cbase = sb + cst * (T96STW * 4);
        G96_STEP(cbase, 0);
    }

#pragma unroll
    for (int mi = 0; mi < 2; mi++) {
        int row = bm + wm + mi * 16 + gr;
#pragma unroll
        for (int ni = 0; ni < 6; ni++) {
            int col = bn + wn + ni * 8 + gc * 2;
            float b0 = __ldg(&bias[col]), b1 = __ldg(&bias[col + 1]);
            float2 v0 = {acc[mi][ni][0] + b0, acc[mi][ni][1] + b1};
            float2 v1 = {acc[mi][ni][2] + b0, acc[mi][ni][3] + b1};
            *(float2*)&C[(size_t)row * N + col] = v0;
            *(float2*)&C[(size_t)(row + 8) * N + col] = v1;
        }
    }
}

// ---------------- QK RMSNorm + RoPE + packed repack ---------------------------
__global__ void __launch_bounds__(256) norm_rope_k(
    const float* __restrict__ pe,
    const float* __restrict__ q_scale, const float* __restrict__ k_scale)
{
    const int half = threadIdx.x >> 7;
    const int t = threadIdx.x & 127;
    const int l = blockIdx.x * 2 + half;
    const int h = blockIdx.y;

    const float* row = g_qkv + (size_t)l * QKV_N + h * HD;
    float qv = row[t], kv = row[DIM + t], vv = row[2 * DIM + t];

    __shared__ float red[2][8];
    __shared__ float qr[2][HD], kr[2][HD], qo_[2][HD], ko_[2][HD], vr[2][HD];

    float s1 = qv * qv, s2 = kv * kv;
#pragma unroll
    for (int o = 16; o > 0; o >>= 1) {
        s1 += __shfl_xor_sync(0xffffffffu, s1, o);
        s2 += __shfl_xor_sync(0xffffffffu, s2, o);
    }
    int w = (t >> 5);
    if ((t & 31) == 0) { red[half][w] = s1; red[half][4 + w] = s2; }
    __syncthreads();
    float msq = (red[half][0] + red[half][1] + red[half][2] + red[half][3]) * (1.f / HD);
    float msk = (red[half][4] + red[half][5] + red[half][6] + red[half][7]) * (1.f / HD);
    qr[half][t] = qv * rsqrtf(msq + 1e-6f) * q_scale[t];
    kr[half][t] = kv * rsqrtf(msk + 1e-6f) * k_scale[t];
    vr[half][t] = vv;
    __syncthreads();

    int i = t >> 1;
    const float* p = pe + ((size_t)l * (HD / 2) + i) * 4;
    float c = p[0], s = p[2];
    float q0 = qr[half][2 * i], q1 = qr[half][2 * i + 1];
    float k0 = kr[half][2 * i], k1 = kr[half][2 * i + 1];
    qo_[half][t] = (t & 1) ? fmaf(s, q0, c * q1) : fmaf(c, q0, -s * q1);
    ko_[half][t] = (t & 1) ? fmaf(s, k0, c * k1) : fmaf(c, k0, -s * k1);
    __syncthreads();

    if (t < 64) {
        size_t base = ((size_t)h * SEQ + l) * (HD / 2) + t;
        float a0 = qo_[half][2 * t], a1 = qo_[half][2 * t + 1];
        unsigned hq = packbf(a0, a1);
        float2 u = unpackbf(hq);
        g_q2h[base] = hq;
        g_q2l[base] = packbf(a0 - u.x, a1 - u.y);
        float b0 = ko_[half][2 * t], b1 = ko_[half][2 * t + 1];
        unsigned hk = packbf(b0, b1);
        u = unpackbf(hk);
        g_k2h[base] = hk;
        g_k2l[base] = packbf(b0 - u.x, b1 - u.y);
    }
    if (half == 0) {
        float v0 = vr[0][t], v1 = vr[1][t];
        unsigned hv = packbf(v0, v1);
        float2 u = unpackbf(hv);
        size_t base = ((size_t)h * HD + t) * SEQW + blockIdx.x;
        g_v2h[base] = hv;
        g_v2l[base] = packbf(v0 - u.x, v1 - u.y);
    }
}

// ---------------- flash attention: reg-Q + 3-stage single-sync pipeline -------
#define FBM 128
#define FBN 64
#define QSW 68
#define VSW 36
#define FKH 0
#define FKL 4352
#define FVH 8704
#define FVL 13312
#define FSTW 17920
#define FNSTG 3
#define FA_SMEM (FNSTG * FSTW * 4)

__global__ void __launch_bounds__(256) flash_k()
{
    extern __shared__ unsigned smf[];
    const unsigned sb = (unsigned)__cvta_generic_to_shared(smf);

    const int h = blockIdx.y;
    const int q0 = blockIdx.x * FBM;
    const int tid = threadIdx.x;
    const int lane = tid & 31, wid = tid >> 5;
    const int gr = lane >> 2, gc = lane & 3;
    const int rb = wid * 16;

    const int aro = lane & 15, aco = (lane >> 4) << 2;
    const int bro = ((lane >> 4) << 3) + (lane & 7), bco = ((lane >> 3) & 1) << 2;

#pragma unroll
    for (int i = 0; i < 8; i++) {
        int idx = tid + i * 256;
        int r = idx >> 4, wq = (idx & 15) * 4;
        size_t src = ((size_t)h * SEQ + q0 + r) * 64 + wq;
        *(uint4*)&smf[r * QSW + wq] = *(const uint4*)&g_q2h[src];
        *(uint4*)&smf[8704 + r * QSW + wq] = *(const uint4*)&g_q2l[src];
    }
    __syncthreads();
    unsigned qfh[8][4], qfl[8][4];
#pragma unroll
    for (int kk = 0; kk < 8; kk++) {
        unsigned qa = sb + ((rb + aro) * QSW + kk * 8 + aco) * 4;
        ldsm4(qfh[kk], qa);
        ldsm4(qfl[kk], qa + 8704 * 4);
    }
    __syncthreads();

#define F_ISSUE(KT, ST) do {                                                \
        unsigned base_ = sb + (ST) * (FSTW * 4);                            \
        _Pragma("unroll")                                                   \
        for (int i_ = 0; i_ < 4; i_++) {                                    \
            int idx_ = tid + i_ * 256;                                      \
            int r_ = idx_ >> 4, wq_ = (idx_ & 15) * 4;                      \
            size_t ks_ = ((size_t)h * SEQ + (KT) + r_) * 64 + wq_;          \
            cpa16(base_ + (FKH + r_ * QSW + wq_) * 4, g_k2h + ks_);         \
            cpa16(base_ + (FKL + r_ * QSW + wq_) * 4, g_k2l + ks_);         \
            int rv_ = idx_ >> 3, wv_ = (idx_ & 7) * 4;                      \
            size_t vs_ = ((size_t)h * HD + rv_) * SEQW + (KT) / 2 + wv_;    \
            cpa16(base_ + (FVH + rv_ * VSW + wv_) * 4, g_v2h + vs_);        \
            cpa16(base_ + (FVL + rv_ * VSW + wv_) * 4, g_v2l + vs_);        \
        }                                                                   \
    } while (0)

    float o[16][4];
#pragma unroll
    for (int i = 0; i < 16; i++)
#pragma unroll
        for (int j = 0; j < 4; j++) o[i][j] = 0.f;
    float m_lo = -1e30f, m_hi = -1e30f, l_lo = 0.f, l_hi = 0.f;
    const float SC2 = 0.088388347648318447f * 1.4426950408889634f;

    F_ISSUE(0, 0);
    CP_COMMIT();
    F_ISSUE(FBN, 1);
    CP_COMMIT();

    const int nkt = SEQ / FBN;
    int ist = 2, cst = 0;
    for (int it = 0; it < nkt; it++) {
        if (it < nkt - 1) CP_WAIT1(); else CP_WAIT0();
        __syncthreads();
        unsigned kbase = sb + cst * (FSTW * 4);

        float s[8][4];
#pragma unroll
        for (int i = 0; i < 8; i++)
#pragma unroll
            for (int j = 0; j < 4; j++) s[i][j] = 0.f;
#pragma unroll
        for (int kk = 0; kk < 8; kk++) {
#pragma unroll
            for (int nj = 0; nj < 4; nj++) {
                unsigned ka = kbase + (FKH + (nj * 16 + bro) * QSW + kk * 8 + bco) * 4;
                unsigned kh[4], kl[4];
                ldsm4(kh, ka);
                ldsm4(kl, ka + (FKL - FKH) * 4);
                mma_bf16(s[2 * nj],     qfh[kk], kh);
                mma_bf16(s[2 * nj],     qfh[kk], kl);
                mma_bf16(s[2 * nj],     qfl[kk], kh);
                mma_bf16(s[2 * nj + 1], qfh[kk], kh + 2);
                mma_bf16(s[2 * nj + 1], qfh[kk], kl + 2);
                mma_bf16(s[2 * nj + 1], qfl[kk], kh + 2);
            }
        }

        if (it + 2 < nkt) {
            F_ISSUE((it + 2) * FBN, ist);
            CP_COMMIT();
        }

        float rl = -1e30f, rh = -1e30f;
#pragma unroll
        for (int ni = 0; ni < 8; ni++) {
            rl = fmaxf(rl, fmaxf(s[ni][0], s[ni][1]));
            rh = fmaxf(rh, fmaxf(s[ni][2], s[ni][3]));
        }
        rl *= SC2; rh *= SC2;
        rl = fmaxf(rl, __shfl_xor_sync(0xffffffffu, rl, 1));
        rl = fmaxf(rl, __shfl_xor_sync(0xffffffffu, rl, 2));
        rh = fmaxf(rh, __shfl_xor_sync(0xffffffffu, rh, 1));
        rh = fmaxf(rh, __shfl_xor_sync(0xffffffffu, rh, 2));
        float mlo = fmaxf(m_lo, rl), mhi = fmaxf(m_hi, rh);
        float clo = exp2t(m_lo - mlo), chi = exp2t(m_hi - mhi);

        float suml = 0.f, sumh = 0.f;
#pragma unroll
        for (int ni = 0; ni < 8; ni++) {
            s[ni][0] = exp2t(fmaf(s[ni][0], SC2, -mlo));
            s[ni][1] = exp2t(fmaf(s[ni][1], SC2, -mlo));
            s[ni][2] = exp2t(fmaf(s[ni][2], SC2, -mhi));
            s[ni][3] = exp2t(fmaf(s[ni][3], SC2, -mhi));
            suml += s[ni][0] + s[ni][1];
            sumh += s[ni][2] + s[ni][3];
        }
        suml += __shfl_xor_sync(0xffffffffu, suml, 1);
        suml += __shfl_xor_sync(0xffffffffu, suml, 2);
        sumh += __shfl_xor_sync(0xffffffffu, sumh, 1);
        sumh += __shfl_xor_sync(0xffffffffu, sumh, 2);
        l_lo = l_lo * clo + suml;
        l_hi = l_hi * chi + sumh;
        m_lo = mlo; m_hi = mhi;

#pragma unroll
        for (int ni = 0; ni < 16; ni++) {
            o[ni][0] *= clo; o[ni][1] *= clo;
            o[ni][2] *= chi; o[ni][3] *= chi;
        }

#pragma unroll
        for (int kk = 0; kk < 4; kk++) {
            unsigned ph[4], pl[4];
            ph[0] = packbf(s[2 * kk][0], s[2 * kk][1]);
            ph[1] = packbf(s[2 * kk][2], s[2 * kk][3]);
            ph[2] = packbf(s[2 * kk + 1][0], s[2 * kk + 1][1]);
            ph[3] = packbf(s[2 * kk + 1][2], s[2 * kk + 1][3]);
            float2 u;
            u = unpackbf(ph[0]); pl[0] = packbf(s[2 * kk][0] - u.x, s[2 * kk][1] - u.y);
            u = unpackbf(ph[1]); pl[1] = packbf(s[2 * kk][2] - u.x, s[2 * kk][3] - u.y);
            u = unpackbf(ph[2]); pl[2] = packbf(s[2 * kk + 1][0] - u.x, s[2 * kk + 1][1] - u.y);
            u = unpackbf(ph[3]); pl[3] = packbf(s[2 * kk + 1][2] - u.x, s[2 * kk + 1][3] - u.y);
#pragma unroll
            for (int nj = 0; nj < 8; nj++) {
                unsigned va = kbase + (FVH + (nj * 16 + bro) * VSW + kk * 8 + bco) * 4;
                unsigned vh[4], vl[4];
                ldsm4(vh, va);
                ldsm4(vl, va + (FVL - FVH) * 4);
                mma_bf16(o[2 * nj],     ph, vh);
                mma_bf16(o[2 * nj],     ph, vl);
                mma_bf16(o[2 * nj],     pl, vh);
                mma_bf16(o[2 * nj + 1], ph, vh + 2);
                mma_bf16(o[2 * nj + 1], ph, vl + 2);
                mma_bf16(o[2 * nj + 1], pl, vh + 2);
            }
        }
        ist = (ist == 2) ? 0 : ist + 1;
        cst = (cst == 2) ? 0 : cst + 1;
    }

    float il = 1.f / l_lo, ih = 1.f / l_hi;
#pragma unroll
    for (int ni = 0; ni < 16; ni++) {
        int row = q0 + rb + gr;
        int col = h * HD + ni * 8 + gc * 2;
        float2 v0 = {o[ni][0] * il, o[ni][1] * il};
        float2 v1 = {o[ni][2] * ih, o[ni][3] * ih};
        *(float2*)&g_o[(size_t)row * DIM + col] = v0;
        *(float2*)&g_o[(size_t)(row + 8) * DIM + col] = v1;

        size_t wi0 = (size_t)row * (DIM / 2) + (col >> 1);
        size_t wi1 = (size_t)(row + 8) * (DIM / 2) + (col >> 1);
        unsigned h0 = packbf(v0.x, v0.y);
        float2 u0 = unpackbf(h0);
        g_o2h[wi0] = h0;
        g_o2l[wi0] = packbf(v0.x - u0.x, v0.y - u0.y);
        unsigned h1 = packbf(v1.x, v1.y);
        float2 u1 = unpackbf(h1);
        g_o2h[wi1] = h1;
        g_o2l[wi1] = packbf(v1.x - u1.x, v1.y - u1.y);
    }
}

// ---------------- launch (serial, R15 order) ----------------------------------
extern "C" void kernel_launch(void* const* d_in, const int* in_sizes, int n_in,
                              void* d_out, int out_size)
{
    const float* x         = (const float*)d_in[0];
    const float* pe        = (const float*)d_in[1];
    const float* qkv_w     = (const float*)d_in[2];
    const float* qkv_b     = (const float*)d_in[3];
    const float* proj_w    = (const float*)d_in[4];
    const float* proj_b    = (const float*)d_in[5];
    const float* qkv_down  = (const float*)d_in[6];
    const float* qkv_up    = (const float*)d_in[7];
    const float* proj_down = (const float*)d_in[8];
    const float* proj_up   = (const float*)d_in[9];
    const float* q_scale   = (const float*)d_in[10];
    const float* k_scale   = (const float*)d_in[11];
    float* out = (float*)d_out;
    (void)in_sizes; (void)n_in; (void)out_size;

    float *gqkv, *go;
    cudaGetSymbolAddress((void**)&gqkv, g_qkv);
    cudaGetSymbolAddress((void**)&go,   g_o);
    unsigned *x2h, *x2l, *w1h, *w1l, *w2h, *w2l, *o2h, *o2l;
    unsigned *u1h, *u1l, *u2h, *u2l, *xa2h, *xa2l, *ob2h, *ob2l;
    cudaGetSymbolAddress((void**)&x2h, g_x2h);   cudaGetSymbolAddress((void**)&x2l, g_x2l);
    cudaGetSymbolAddress((void**)&w1h, g_w1h);   cudaGetSymbolAddress((void**)&w1l, g_w1l);
    cudaGetSymbolAddress((void**)&w2h, g_w2h);   cudaGetSymbolAddress((void**)&w2l, g_w2l);
    cudaGetSymbolAddress((void**)&o2h, g_o2h);   cudaGetSymbolAddress((void**)&o2l, g_o2l);
    cudaGetSymbolAddress((void**)&u1h, g_u1h);   cudaGetSymbolAddress((void**)&u1l, g_u1l);
    cudaGetSymbolAddress((void**)&u2h, g_u2h);   cudaGetSymbolAddress((void**)&u2l, g_u2l);
    cudaGetSymbolAddress((void**)&xa2h, g_xa2h); cudaGetSymbolAddress((void**)&xa2l, g_xa2l);
    cudaGetSymbolAddress((void**)&ob2h, g_ob2h); cudaGetSymbolAddress((void**)&ob2l, g_ob2l);

    cudaFuncSetAttribute(flash_k, cudaFuncAttributeMaxDynamicSharedMemorySize,
                         (int)FA_SMEM);
    cudaFuncSetAttribute(gemm_bf16s_lora_k, cudaFuncAttributeMaxDynamicSharedMemorySize,
                         (int)GEMM_SMEM);
    cudaFuncSetAttribute(gemm96_bf16s_lora_k, cudaFuncAttributeMaxDynamicSharedMemorySize,
                         (int)GEMM96_SMEM);

    const int n4x  = (int)((size_t)SEQ * DIM / 4);
    const int n4w1 = (int)((size_t)QKV_N * DIM / 4);
    const int n4u1 = QKV_N * RANK / 4;
    const int n4w2 = (int)((size_t)DIM * DIM / 4);
    const int n4u2 = DIM * RANK / 4;

    // 0: pack x
    convert_pack_k<<<(n4x + 255) / 256, 256>>>((const float4*)x, x2h, x2l, n4x);
    // 1: lora-down(x) + fused pack (256 CTAs x 128 threads)
    lora_down_pack_k<<<SEQ / 8, 128>>>(x, qkv_down, xa2h, xa2l);
    // 2: pack qkv_w + qkv_up
    convert_pack2_k<<<(n4w1 + n4u1 + 255) / 256, 256>>>(
        (const float4*)qkv_w, w1h, w1l, n4w1,
        (const float4*)qkv_up, u1h, u1l, n4u1);
    // 3: qkv GEMM  <-- profiled launch index
    gemm_bf16s_lora_k<<<dim3(QKV_N / 128, SEQ / 128), 256, GEMM_SMEM>>>(
        x2h, x2l, w1h, w1l, qkv_b, xa2h, xa2l, u1h, u1l, gqkv, QKV_N, DIM);
    // 4: pack proj_w + proj_up
    convert_pack2_k<<<(n4w2 + n4u2 + 255) / 256, 256>>>(
        (const float4*)proj_w, w2h, w2l, n4w2,
        (const float4*)proj_up, u2h, u2l, n4u2);
    // 5: norm + rope + repack
    norm_rope_k<<<dim3(SEQ / 2, NH), 256>>>(pe, q_scale, k_scale);
    // 6: flash attention (reg-Q, 3-stage, single sync)
    flash_k<<<dim3(SEQ / FBM, NH), 256, FA_SMEM>>>();
    // 7: lora-down(o) + fused pack
    lora_down_pack_k<<<SEQ / 8, 128>>>(go, proj_down, ob2h, ob2l);
    // 8: proj GEMM (96-wide N tiles)
    gemm96_bf16s_lora_k<<<dim3(DIM / 96, SEQ / 128), 256, GEMM96_SMEM>>>(
        o2h, o2l, w2h, w2l, proj_b, ob2h, ob2l, u2h, u2l, out, DIM, DIM);
}